// round 1
// baseline (speedup 1.0000x reference)
#include <cuda_runtime.h>
#include <cuda_bf16.h>
#include <math.h>
#include <float.h>

#define HH 320
#define WW 512
#define HW (HH * WW)
#define NDISP 64
#define RAD 10          // BLOCK=21 -> radius 10
#define NIMGB 4         // (img in {x,gt}) * (b in {0,1})

// Scratch (device globals -- allocation-free rule)
__device__ float g_norm[NIMGB * 6 * HW];          // normalized L/R, 15.7 MB
__device__ float g_V[NIMGB * NDISP * HW];         // vertical box sums, 168 MB
__device__ float g_disp[NIMGB * HW];              // disparity maps (as float)
__device__ float g_part[256];                     // reduction partials

// ---------------------------------------------------------------------------
// K1: per-pixel 3-channel L2 normalize of left (ch 0..2) and right (ch 3..5)
// for both inputs. One thread per (imgb, side, pixel).
// ---------------------------------------------------------------------------
__global__ void knorm(const float* __restrict__ x, const float* __restrict__ gt) {
    int idx = blockIdx.x * blockDim.x + threadIdx.x;
    const int total = NIMGB * 2 * HW;
    if (idx >= total) return;
    int pix  = idx % HW;
    int rest = idx / HW;
    int side = rest & 1;
    int imgb = rest >> 1;
    int img  = imgb >> 1;
    int b    = imgb & 1;

    const float* src = img ? gt : x;
    int base = (b * 6 + side * 3) * HW + pix;
    float v0 = src[base];
    float v1 = src[base + HW];
    float v2 = src[base + 2 * HW];
    float n = sqrtf(v0 * v0 + v1 * v1 + v2 * v2);
    float inv = 1.0f / fmaxf(n, 1e-12f);
    int dst = (imgb * 6 + side * 3) * HW + pix;
    g_norm[dst]          = v0 * inv;
    g_norm[dst + HW]     = v1 * inv;
    g_norm[dst + 2 * HW] = v2 * inv;
}

// ---------------------------------------------------------------------------
// K2: vertical 21-tap box sum of the per-disparity SAD, computed on the fly.
// Thread = fixed (imgb, d, w); sliding window over h with circular smem buffer.
// grid (W/128, NDISP, NIMGB), 128 threads.
// ---------------------------------------------------------------------------
__global__ void kvert() {
    int tid  = threadIdx.x;
    int w    = blockIdx.x * 128 + tid;
    int d    = blockIdx.y;
    int imgb = blockIdx.z;

    const float* __restrict__ L = g_norm + imgb * 6 * HW;       // ch 0..2
    const float* __restrict__ R = L + 3 * HW;                   // ch 3..5
    float* __restrict__ V = g_V + (imgb * NDISP + d) * HW;

    __shared__ float buf[21][128];

    int rw = w - d;
    bool valid = (rw >= 0);
    float run = 0.0f;
    int slot = 0;

#pragma unroll 2
    for (int j = 0; j < HH + RAD; ++j) {
        float dn = 0.0f;
        if (j < HH) {
            int o = j * WW + w;
            float l0 = L[o];
            float l1 = L[o + HW];
            float l2 = L[o + 2 * HW];
            float r0 = 0.0f, r1 = 0.0f, r2 = 0.0f;
            if (valid) {
                int orr = j * WW + rw;
                r0 = R[orr];
                r1 = R[orr + HW];
                r2 = R[orr + 2 * HW];
            }
            dn = fabsf(l0 - r0) + fabsf(l1 - r1) + fabsf(l2 - r2);
        }
        float old = buf[slot][tid];
        buf[slot][tid] = dn;
        run += dn - ((j >= 21) ? old : 0.0f);
        int h = j - RAD;
        if (h >= 0) V[h * WW + w] = run;
        if (++slot == 21) slot = 0;
    }
}

// ---------------------------------------------------------------------------
// K3: horizontal 21-tap box + argmin over d.
// CTA = (imgb, 8-row tile). 512 threads: hloc = t>>6, each thread owns 8
// consecutive w with a per-thread horizontal sliding sum from smem.
// Smem padded w -> w + (w>>3): lane stride-8 becomes 9*lane mod 32 (conflict-free).
// ---------------------------------------------------------------------------
#define PADW(q) ((q) + ((q) >> 3))
#define ROWSTR 576   // 512 + 64 padding

__global__ void khoriz() {
    __shared__ float rows[8 * ROWSTR];

    int t     = threadIdx.x;
    int imgb  = blockIdx.y;
    int h0    = blockIdx.x * 8;
    int hloc  = t >> 6;
    int c     = t & 63;
    int wbase = c * 8;

    float bestc[8];
    int   bestd[8];
#pragma unroll
    for (int i = 0; i < 8; ++i) { bestc[i] = FLT_MAX; bestd[i] = 0; }

    const float* __restrict__ Vb = g_V + imgb * NDISP * HW;

    for (int d = 0; d < NDISP; ++d) {
        __syncthreads();
        const float* __restrict__ Vd = Vb + d * HW + h0 * WW;
#pragma unroll
        for (int r = 0; r < 8; ++r)
            rows[r * ROWSTR + PADW(t)] = Vd[r * WW + t];
        __syncthreads();

        const float* row = &rows[hloc * ROWSTR];
        // initial window for w = wbase: [wbase-10, wbase+10] clamped
        float s = 0.0f;
        int lo = wbase - RAD; if (lo < 0) lo = 0;
        int hi = wbase + RAD; if (hi > WW - 1) hi = WW - 1;
        for (int ww = lo; ww <= hi; ++ww) s += row[PADW(ww)];

        int w = wbase;
#pragma unroll
        for (int i = 0; i < 8; ++i) {
            if (s < bestc[i]) { bestc[i] = s; bestd[i] = d; }
            // slide window to w+1: add (w+11), remove (w-10)
            int add = w + RAD + 1;
            int sub = w - RAD;
            if (add < WW) s += row[PADW(add)];
            if (sub >= 0) s -= row[PADW(sub)];
            ++w;
        }
    }

    float* __restrict__ D = g_disp + imgb * HW + (h0 + hloc) * WW + wbase;
#pragma unroll
    for (int i = 0; i < 8; ++i) D[i] = (float)bestd[i];
}

// ---------------------------------------------------------------------------
// K4: per-block partial sums of |disp_x - disp_gt| (deterministic).
// disp_x = imgb 0..1 -> g_disp[0 .. 2*HW), disp_gt = imgb 2..3.
// ---------------------------------------------------------------------------
__global__ void kred1() {
    __shared__ float sm[256];
    const int N = 2 * HW;    // 327680 pixels total
    int tid = threadIdx.x;
    float s = 0.0f;
    for (int p = blockIdx.x * 256 + tid; p < N; p += 256 * 256)
        s += fabsf(g_disp[p] - g_disp[2 * HW + p]);
    sm[tid] = s;
    __syncthreads();
    for (int o = 128; o > 0; o >>= 1) {
        if (tid < o) sm[tid] += sm[tid + o];
        __syncthreads();
    }
    if (tid == 0) g_part[blockIdx.x] = sm[0];
}

__global__ void kred2(float* __restrict__ out) {
    __shared__ float sm[256];
    int tid = threadIdx.x;
    sm[tid] = g_part[tid];
    __syncthreads();
    for (int o = 128; o > 0; o >>= 1) {
        if (tid < o) sm[tid] += sm[tid + o];
        __syncthreads();
    }
    if (tid == 0) out[0] = sm[0] / (float)(2 * HW);
}

// ---------------------------------------------------------------------------
extern "C" void kernel_launch(void* const* d_in, const int* in_sizes, int n_in,
                              void* d_out, int out_size) {
    const float* x  = (const float*)d_in[0];
    const float* gt = (const float*)d_in[1];
    float* out = (float*)d_out;

    int nNorm = NIMGB * 2 * HW;
    knorm<<<(nNorm + 255) / 256, 256>>>(x, gt);
    kvert<<<dim3(WW / 128, NDISP, NIMGB), 128>>>();
    khoriz<<<dim3(HH / 8, NIMGB), 512>>>();
    kred1<<<256, 256>>>();
    kred2<<<1, 256>>>(out);
}